// round 6
// baseline (speedup 1.0000x reference)
#include <cuda_runtime.h>
#include <cuda_bf16.h>
#include <stdint.h>
#include <math.h>

#define BB   8
#define SS   2048
#define HH   256
#define NHH  4
#define HDD  64
#define MTOT (BB * SS)   // 16384

// ---------------------------------------------------------------------------
// Scratch (__device__ globals only).
// ---------------------------------------------------------------------------
__device__ __align__(128) __nv_bfloat16 g_Qb[32 * SS * HDD];   // [bh][s][d]
__device__ __align__(128) __nv_bfloat16 g_Kb[32 * SS * HDD];   // [bh][s][d]
__device__ __align__(128) __nv_bfloat16 g_Vb[32 * SS * HDD];   // [bh][s][d] row-major
__device__ __align__(128) __nv_bfloat16 g_ctxb[MTOT * HH];     // [m][h*64+d]
__device__ __align__(128) float         g_resid[MTOT * HH];

// ---------------------------------------------------------------------------
// Helpers
// ---------------------------------------------------------------------------
__device__ __forceinline__ uint32_t packbf(float lo, float hi) {
    uint32_t r;
    asm("cvt.rn.bf16x2.f32 %0, %1, %2;" : "=r"(r) : "f"(hi), "f"(lo));
    return r;
}

__device__ __forceinline__ float ex2(float x) {
    float y;
    asm("ex2.approx.ftz.f32 %0, %1;" : "=f"(y) : "f"(x));
    return y;
}

__device__ __forceinline__ void mma16816(float* c, const uint32_t* a, const uint32_t* b) {
    asm volatile(
        "mma.sync.aligned.m16n8k16.row.col.f32.bf16.bf16.f32 "
        "{%0,%1,%2,%3}, {%4,%5,%6,%7}, {%8,%9}, {%0,%1,%2,%3};\n"
        : "+f"(c[0]), "+f"(c[1]), "+f"(c[2]), "+f"(c[3])
        : "r"(a[0]), "r"(a[1]), "r"(a[2]), "r"(a[3]), "r"(b[0]), "r"(b[1]));
}

__device__ __forceinline__ uint32_t smem_u32(const void* p) {
    uint32_t a;
    asm("{ .reg .u64 t; cvta.to.shared.u64 t, %1; cvt.u32.u64 %0, t; }" : "=r"(a) : "l"(p));
    return a;
}

__device__ __forceinline__ void ldsm4(uint32_t& r0, uint32_t& r1, uint32_t& r2, uint32_t& r3,
                                      uint32_t addr) {
    asm volatile("ldmatrix.sync.aligned.m8n8.x4.shared.b16 {%0,%1,%2,%3}, [%4];"
                 : "=r"(r0), "=r"(r1), "=r"(r2), "=r"(r3) : "r"(addr));
}

__device__ __forceinline__ void ldsm4t(uint32_t& r0, uint32_t& r1, uint32_t& r2, uint32_t& r3,
                                       uint32_t addr) {
    asm volatile("ldmatrix.sync.aligned.m8n8.x4.trans.shared.b16 {%0,%1,%2,%3}, [%4];"
                 : "=r"(r0), "=r"(r1), "=r"(r2), "=r"(r3) : "r"(addr));
}

__device__ __forceinline__ void cp16(uint32_t dst, const void* src) {
    asm volatile("cp.async.cg.shared.global [%0], [%1], 16;" :: "r"(dst), "l"(src));
}
#define CP_COMMIT() asm volatile("cp.async.commit_group;" ::: "memory")
#define CP_WAIT1()  asm volatile("cp.async.wait_group 1;" ::: "memory")
#define CP_WAIT0()  asm volatile("cp.async.wait_group 0;" ::: "memory")

#define GP 40   // smem pitch for mma.sync GEMM tiles (qkv/proj)

// ---------------------------------------------------------------------------
// Kernel 1: QKV projection (bf16 mma.sync). All three outputs row-major.
// ---------------------------------------------------------------------------
__global__ __launch_bounds__(128) void qkv_kernel(
    const float* __restrict__ X,
    const float* __restrict__ Wq, const float* __restrict__ bq,
    const float* __restrict__ Wk, const float* __restrict__ bk,
    const float* __restrict__ Wv, const float* __restrict__ bv)
{
    __shared__ __nv_bfloat16 As[128 * GP];
    __shared__ __nv_bfloat16 Bs[64 * GP];

    const int z = blockIdx.z;
    const float* W;  const float* bias;  __nv_bfloat16* out;
    if (z == 0)      { W = Wq; bias = bq; out = g_Qb; }
    else if (z == 1) { W = Wk; bias = bk; out = g_Kb; }
    else             { W = Wv; bias = bv; out = g_Vb; }

    const int t = threadIdx.x;
    const int w = t >> 5, lane = t & 31;
    const int g = lane >> 2, tig = lane & 3;
    const int m0 = blockIdx.y * 128, n0 = blockIdx.x * 64;

    float c[2][8][4];
    #pragma unroll
    for (int mt = 0; mt < 2; mt++)
        #pragma unroll
        for (int j = 0; j < 8; j++)
            #pragma unroll
            for (int i = 0; i < 4; i++) c[mt][j][i] = 0.0f;

    for (int k0 = 0; k0 < HH; k0 += 32) {
        #pragma unroll
        for (int i = 0; i < 8; i++) {
            int m = (t >> 3) + 16 * i;
            int k = 4 * (t & 7);
            float4 v = *(const float4*)(X + (m0 + m) * HH + k0 + k);
            uint2 p;
            p.x = packbf(v.x, v.y);
            p.y = packbf(v.z, v.w);
            *(uint2*)&As[m * GP + k] = p;
        }
        #pragma unroll
        for (int i = 0; i < 8; i++) {
            int idx = 2 * t + 256 * i;
            int k = idx >> 6, n = idx & 63;
            float2 v = *(const float2*)(W + (k0 + k) * HH + n0 + n);
            Bs[n * GP + k]       = __float2bfloat16(v.x);
            Bs[(n + 1) * GP + k] = __float2bfloat16(v.y);
        }
        __syncthreads();

        uint32_t a[2][2][4];
        #pragma unroll
        for (int mt = 0; mt < 2; mt++)
            #pragma unroll
            for (int kt = 0; kt < 2; kt++) {
                int r = w * 32 + mt * 16;
                a[mt][kt][0] = *(const uint32_t*)&As[(r + g)     * GP + kt * 16 + 2 * tig];
                a[mt][kt][1] = *(const uint32_t*)&As[(r + g + 8) * GP + kt * 16 + 2 * tig];
                a[mt][kt][2] = *(const uint32_t*)&As[(r + g)     * GP + kt * 16 + 2 * tig + 8];
                a[mt][kt][3] = *(const uint32_t*)&As[(r + g + 8) * GP + kt * 16 + 2 * tig + 8];
            }
        #pragma unroll
        for (int j = 0; j < 8; j++) {
            #pragma unroll
            for (int kt = 0; kt < 2; kt++) {
                uint32_t b[2];
                b[0] = *(const uint32_t*)&Bs[(8 * j + g) * GP + kt * 16 + 2 * tig];
                b[1] = *(const uint32_t*)&Bs[(8 * j + g) * GP + kt * 16 + 2 * tig + 8];
                mma16816(c[0][j], a[0][kt], b);
                mma16816(c[1][j], a[1][kt], b);
            }
        }
        __syncthreads();
    }

    const int head = blockIdx.x;
    #pragma unroll
    for (int mt = 0; mt < 2; mt++) {
        int r0 = m0 + w * 32 + mt * 16 + g;
        #pragma unroll
        for (int half = 0; half < 2; half++) {
            int m  = r0 + half * 8;
            int b_ = m >> 11;
            int s_ = m & (SS - 1);
            int bh = b_ * NHH + head;
            #pragma unroll
            for (int j = 0; j < 8; j++) {
                int d = 8 * j + 2 * tig;
                float v0 = c[mt][j][half * 2 + 0] + bias[n0 + d];
                float v1 = c[mt][j][half * 2 + 1] + bias[n0 + d + 1];
                *(uint32_t*)&out[(bh * SS + s_) * HDD + d] = packbf(v0, v1);
            }
        }
    }
}

// ---------------------------------------------------------------------------
// Kernel 2: flash attention, bf16 mma.sync, BQ=128 (32 rows/warp), BK=64.
// R4 pipeline (2-buffer cp.async, wait_group 1, prefetch after compute),
// V row-major tile + ldmatrix.trans for PV, no-max softmax via ex2.
// ---------------------------------------------------------------------------
#define NIT 32   // SS / 64

struct __align__(1024) AttnSmem {
    __nv_bfloat16 K[2][64 * 64];
    __nv_bfloat16 V[2][64 * 64];
};

__global__ __launch_bounds__(128) void attn_kernel(const float* __restrict__ mask)
{
    __shared__ AttnSmem sm;

    const int t = threadIdx.x;
    const int w = t >> 5, lane = t & 31;
    const int g = lane >> 2, tig = lane & 3;
    const int bh = blockIdx.x;
    const int qb = blockIdx.y;
    const int b_ = bh >> 2;
    const int h_ = bh & 3;

    const uint32_t kbase[2] = { smem_u32(&sm.K[0][0]), smem_u32(&sm.K[1][0]) };
    const uint32_t vbase[2] = { smem_u32(&sm.V[0][0]), smem_u32(&sm.V[1][0]) };

    const __nv_bfloat16* Qg = g_Qb + (size_t)bh * SS * HDD;
    const char* Kg = (const char*)(g_Kb + (size_t)bh * SS * HDD);
    const char* Vg = (const char*)(g_Vb + (size_t)bh * SS * HDD);
    const float* Mb = mask + (size_t)b_ * SS * SS;

    // cp.async chunk addressing: chunk c = t + 128*jc -> row (0..63), seg (0..7)
    int ld_src[4], ld_dst[4];
    #pragma unroll
    for (int jc = 0; jc < 4; jc++) {
        int c = t + 128 * jc;
        int row = c >> 3, seg = c & 7;
        ld_src[jc] = row * 128 + seg * 16;
        ld_dst[jc] = row * 128 + ((seg * 16) ^ ((row & 7) * 16));
    }

    // K (scores) ldmatrix addressing: B[n=kv][k=d] direct
    const int lrow = (lane & 7) | ((lane & 16) >> 1);
    const int lkb  = (lane & 8) ? 16 : 0;
    const int lxor = (lrow & 7) * 16;
    const int lbase = lrow * 128;

    // V (PV) ldmatrix.trans addressing on row-major [kv][d] tile
    const int vrow  = (lane & 7) + ((lane & 8) ? 8 : 0);
    const int vcol  = (lane & 16);              // 0 or 16 bytes within d-block
    const int vxor  = (vrow & 7) * 16;
    const int vroff = vrow * 128;

    // Q A-fragments (2 m-tiles of 16 rows), resident all iterations
    const int qrow[2] = { qb * 128 + w * 32 + g, qb * 128 + w * 32 + 16 + g };
    uint32_t aq[2][4][4];
    #pragma unroll
    for (int mt = 0; mt < 2; mt++) {
        const __nv_bfloat16* r0 = Qg + (size_t)qrow[mt] * HDD;
        const __nv_bfloat16* r1 = r0 + 8 * HDD;
        #pragma unroll
        for (int kt = 0; kt < 4; kt++) {
            aq[mt][kt][0] = *(const uint32_t*)(r0 + kt * 16 + 2 * tig);
            aq[mt][kt][1] = *(const uint32_t*)(r1 + kt * 16 + 2 * tig);
            aq[mt][kt][2] = *(const uint32_t*)(r0 + kt * 16 + 2 * tig + 8);
            aq[mt][kt][3] = *(const uint32_t*)(r1 + kt * 16 + 2 * tig + 8);
        }
    }

    // prologue: issue K/V tiles 0 and 1
    #pragma unroll
    for (int it = 0; it < 2; it++) {
        const char* Ks = Kg + (size_t)it * 64 * 128;
        const char* Vs = Vg + (size_t)it * 64 * 128;
        #pragma unroll
        for (int jc = 0; jc < 4; jc++) {
            cp16(kbase[it] + ld_dst[jc], Ks + ld_src[jc]);
            cp16(vbase[it] + ld_dst[jc], Vs + ld_src[jc]);
        }
        CP_COMMIT();
    }

    float o[2][8][4];
    #pragma unroll
    for (int mt = 0; mt < 2; mt++)
        #pragma unroll
        for (int j = 0; j < 8; j++)
            #pragma unroll
            for (int i = 0; i < 4; i++) o[mt][j][i] = 0.0f;
    float lacc[2][2] = {{0.0f, 0.0f}, {0.0f, 0.0f}};

    const float SC = 0.18033688f;           // 0.125 * log2(e)
    const float LOG2E = 1.4426950408889634f;

    for (int i = 0; i < NIT; i++) {
        const int buf = i & 1;
        if (i < NIT - 1) { CP_WAIT1(); } else { CP_WAIT0(); }
        __syncthreads();

        // ---- S = Q @ K^T ----
        float c[2][8][4];
        #pragma unroll
        for (int mt = 0; mt < 2; mt++)
            #pragma unroll
            for (int j = 0; j < 8; j++)
                #pragma unroll
                for (int q = 0; q < 4; q++) c[mt][j][q] = 0.0f;

        #pragma unroll
        for (int jj = 0; jj < 4; jj++) {
            #pragma unroll
            for (int kt = 0; kt < 4; kt++) {
                uint32_t r0, r1, r2, r3;
                ldsm4(r0, r1, r2, r3,
                      kbase[buf] + jj * 2048 + lbase + ((kt * 32 + lkb) ^ lxor));
                uint32_t blo[2] = { r0, r1 }, bhi[2] = { r2, r3 };
                mma16816(c[0][2 * jj],     aq[0][kt], blo);
                mma16816(c[0][2 * jj + 1], aq[0][kt], bhi);
                mma16816(c[1][2 * jj],     aq[1][kt], blo);
                mma16816(c[1][2 * jj + 1], aq[1][kt], bhi);
            }
        }

        // ---- softmax (no max): p = 2^(s*SC + m*log2e) ----
        uint32_t pa[2][4][4];
        #pragma unroll
        for (int mt = 0; mt < 2; mt++) {
            const float* mp0 = Mb + (size_t)qrow[mt] * SS + i * 64 + 2 * tig;
            const float* mp1 = mp0 + 8 * SS;
            float2 mk0[8], mk1[8];
            #pragma unroll
            for (int j = 0; j < 8; j++) {
                mk0[j] = *(const float2*)(mp0 + 8 * j);
                mk1[j] = *(const float2*)(mp1 + 8 * j);
                mk0[j].x *= LOG2E; mk0[j].y *= LOG2E;
                mk1[j].x *= LOG2E; mk1[j].y *= LOG2E;
            }
            #pragma unroll
            for (int j = 0; j < 8; j++) {
                float p0 = ex2(fmaf(c[mt][j][0], SC, mk0[j].x));
                float p1 = ex2(fmaf(c[mt][j][1], SC, mk0[j].y));
                float p2 = ex2(fmaf(c[mt][j][2], SC, mk1[j].x));
                float p3 = ex2(fmaf(c[mt][j][3], SC, mk1[j].y));
                lacc[mt][0] += p0 + p1;
                lacc[mt][1] += p2 + p3;
                int kt = j >> 1, hi = (j & 1) * 2;
                pa[mt][kt][hi + 0] = packbf(p0, p1);
                pa[mt][kt][hi + 1] = packbf(p2, p3);
            }
        }

        // ---- O += P @ V (B-frags via ldmatrix.trans on [kv][d] tile) ----
        #pragma unroll
        for (int jj = 0; jj < 4; jj++) {
            #pragma unroll
            for (int kt = 0; kt < 4; kt++) {
                uint32_t r0, r1, r2, r3;
                ldsm4t(r0, r1, r2, r3,
                       vbase[buf] + kt * 2048 + vroff + ((jj * 32 + vcol) ^ vxor));
                uint32_t blo[2] = { r0, r1 }, bhi[2] = { r2, r3 };
                mma16816(o[0][2 * jj],     pa[0][kt], blo);
                mma16816(o[0][2 * jj + 1], pa[0][kt], bhi);
                mma16816(o[1][2 * jj],     pa[1][kt], blo);
                mma16816(o[1][2 * jj + 1], pa[1][kt], bhi);
            }
        }

        __syncthreads();   // everyone done reading buf before it is overwritten

        if (i + 2 < NIT) {
            const char* Ks = Kg + (size_t)(i + 2) * 64 * 128;
            const char* Vs = Vg + (size_t)(i + 2) * 64 * 128;
            #pragma unroll
            for (int jc = 0; jc < 4; jc++) {
                cp16(kbase[buf] + ld_dst[jc], Ks + ld_src[jc]);
                cp16(vbase[buf] + ld_dst[jc], Vs + ld_src[jc]);
            }
            CP_COMMIT();
        }
    }

    // ---- final: reduce l across the 4 lanes of each row group, write ctx ----
    #pragma unroll
    for (int mt = 0; mt < 2; mt++)
        #pragma unroll
        for (int h = 0; h < 2; h++) {
            float v = lacc[mt][h];
            v += __shfl_xor_sync(0xffffffffu, v, 1);
            v += __shfl_xor_sync(0xffffffffu, v, 2);
            lacc[mt][h] = 1.0f / v;
        }

    #pragma unroll
    for (int mt = 0; mt < 2; mt++) {
        __nv_bfloat16* c0 = g_ctxb + ((size_t)b_ * SS + qrow[mt]) * HH + h_ * HDD;
        __nv_bfloat16* c1 = c0 + 8 * HH;
        #pragma unroll
        for (int j = 0; j < 8; j++) {
            int d = 8 * j + 2 * tig;
            *(uint32_t*)(c0 + d) = packbf(o[mt][j][0] * lacc[mt][0],
                                          o[mt][j][1] * lacc[mt][0]);
            *(uint32_t*)(c1 + d) = packbf(o[mt][j][2] * lacc[mt][1],
                                          o[mt][j][3] * lacc[mt][1]);
        }
    }
}

// ---------------------------------------------------------------------------
// Kernel 3: out projection + residual (bf16 mma.sync, unchanged)
// ---------------------------------------------------------------------------
__global__ __launch_bounds__(128) void proj_kernel(
    const float* __restrict__ X,
    const float* __restrict__ Wo, const float* __restrict__ bo)
{
    __shared__ __nv_bfloat16 As[128 * GP];
    __shared__ __nv_bfloat16 Bs[64 * GP];

    const int t = threadIdx.x;
    const int w = t >> 5, lane = t & 31;
    const int g = lane >> 2, tig = lane & 3;
    const int m0 = blockIdx.y * 128, n0 = blockIdx.x * 64;

    float c[2][8][4];
    #pragma unroll
    for (int mt = 0; mt < 2; mt++)
        #pragma unroll
        for (int j = 0; j < 8; j++)
            #pragma unroll
            for (int i = 0; i < 4; i++) c[mt][j][i] = 0.0f;

    for (int k0 = 0; k0 < HH; k0 += 32) {
        #pragma unroll
        for (int i = 0; i < 4; i++) {
            int m = (t >> 2) + 32 * i;
            int k = 8 * (t & 3);
            *(uint4*)&As[m * GP + k] =
                *(const uint4*)&g_ctxb[(m0 + m) * HH + k0 + k];
        }
        #pragma unroll
        for (int i = 0; i < 8; i++) {
            int idx = 2 * t + 256 * i;
            int k = idx >> 6, n = idx & 63;
            float2 v = *(const float2*)(Wo + (k0 + k) * HH + n0 + n);
            Bs[n * GP + k]       = __float2bfloat16(v.x);
            Bs[(n + 1) * GP + k] = __float2bfloat16(v.y);
        }
        __syncthreads();

        uint32_t a[2][2][4];
        #pragma unroll
        for (int mt = 0; mt < 2; mt++)
            #pragma unroll
            for (int kt = 0; kt < 2; kt++) {
                int r = w * 32 + mt * 16;
                a[mt][kt][0] = *(const uint32_t*)&As[(r + g)     * GP + kt * 16 + 2 * tig];
                a[mt][kt][1] = *(const uint32_t*)&As[(r + g + 8) * GP + kt * 16 + 2 * tig];
                a[mt][kt][2] = *(const uint32_t*)&As[(r + g)     * GP + kt * 16 + 2 * tig + 8];
                a[mt][kt][3] = *(const uint32_t*)&As[(r + g + 8) * GP + kt * 16 + 2 * tig + 8];
            }
        #pragma unroll
        for (int j = 0; j < 8; j++) {
            #pragma unroll
            for (int kt = 0; kt < 2; kt++) {
                uint32_t b[2];
                b[0] = *(const uint32_t*)&Bs[(8 * j + g) * GP + kt * 16 + 2 * tig];
                b[1] = *(const uint32_t*)&Bs[(8 * j + g) * GP + kt * 16 + 2 * tig + 8];
                mma16816(c[0][j], a[0][kt], b);
                mma16816(c[1][j], a[1][kt], b);
            }
        }
        __syncthreads();
    }

    #pragma unroll
    for (int mt = 0; mt < 2; mt++) {
        int r0 = m0 + w * 32 + mt * 16 + g;
        #pragma unroll
        for (int half = 0; half < 2; half++) {
            int m = r0 + half * 8;
            #pragma unroll
            for (int j = 0; j < 8; j++) {
                int n = n0 + 8 * j + 2 * tig;
                float2 xr = *(const float2*)(X + m * HH + n);
                float2 ov;
                ov.x = c[mt][j][half * 2 + 0] + bo[n]     + xr.x;
                ov.y = c[mt][j][half * 2 + 1] + bo[n + 1] + xr.y;
                *(float2*)&g_resid[m * HH + n] = ov;
            }
        }
    }
}

// ---------------------------------------------------------------------------
// Kernel 4: LayerNorm (unchanged)
// ---------------------------------------------------------------------------
__global__ __launch_bounds__(256) void ln_kernel(
    const float* __restrict__ gamma, const float* __restrict__ beta,
    float* __restrict__ out)
{
    const int lane = threadIdx.x & 31;
    const int warp = threadIdx.x >> 5;
    const int row  = blockIdx.x * 8 + warp;

    const float* r = g_resid + row * HH + lane * 8;
    float4 a  = *(const float4*)(r);
    float4 b4 = *(const float4*)(r + 4);

    float sum = a.x + a.y + a.z + a.w + b4.x + b4.y + b4.z + b4.w;
    #pragma unroll
    for (int off = 16; off; off >>= 1)
        sum += __shfl_xor_sync(0xffffffffu, sum, off);
    float mu = sum * (1.0f / 256.0f);

    float d0 = a.x - mu, d1 = a.y - mu, d2 = a.z - mu, d3 = a.w - mu;
    float d4 = b4.x - mu, d5 = b4.y - mu, d6 = b4.z - mu, d7 = b4.w - mu;
    float vs = d0 * d0 + d1 * d1 + d2 * d2 + d3 * d3
             + d4 * d4 + d5 * d5 + d6 * d6 + d7 * d7;
    #pragma unroll
    for (int off = 16; off; off >>= 1)
        vs += __shfl_xor_sync(0xffffffffu, vs, off);
    float inv = rsqrtf(vs * (1.0f / 256.0f) + 1e-12f);

    float4 g0 = *(const float4*)(gamma + lane * 8);
    float4 g1 = *(const float4*)(gamma + lane * 8 + 4);
    float4 e0 = *(const float4*)(beta + lane * 8);
    float4 e1 = *(const float4*)(beta + lane * 8 + 4);

    float4 o0, o1;
    o0.x = d0 * inv * g0.x + e0.x;
    o0.y = d1 * inv * g0.y + e0.y;
    o0.z = d2 * inv * g0.z + e0.z;
    o0.w = d3 * inv * g0.w + e0.w;
    o1.x = d4 * inv * g1.x + e1.x;
    o1.y = d5 * inv * g1.y + e1.y;
    o1.z = d6 * inv * g1.z + e1.z;
    o1.w = d7 * inv * g1.w + e1.w;

    float* op = out + row * HH + lane * 8;
    *(float4*)(op)     = o0;
    *(float4*)(op + 4) = o1;
}

// ---------------------------------------------------------------------------
extern "C" void kernel_launch(void* const* d_in, const int* in_sizes, int n_in,
                              void* d_out, int out_size)
{
    const float* X     = (const float*)d_in[0];
    const float* mask  = (const float*)d_in[1];
    const float* Wq    = (const float*)d_in[2];
    const float* bq    = (const float*)d_in[3];
    const float* Wk    = (const float*)d_in[4];
    const float* bk    = (const float*)d_in[5];
    const float* Wv    = (const float*)d_in[6];
    const float* bv    = (const float*)d_in[7];
    const float* Wo    = (const float*)d_in[8];
    const float* bo    = (const float*)d_in[9];
    const float* gamma = (const float*)d_in[10];
    const float* beta  = (const float*)d_in[11];
    float* out = (float*)d_out;

    qkv_kernel<<<dim3(HH / 64, MTOT / 128, 3), 128>>>(X, Wq, bq, Wk, bk, Wv, bv);
    attn_kernel<<<dim3(BB * NHH, SS / 128), 128>>>(mask);
    proj_kernel<<<dim3(HH / 64, MTOT / 128), 128>>>(X, Wo, bo);
    ln_kernel<<<MTOT / 8, 256>>>(gamma, beta, out);
}

// round 7
// speedup vs baseline: 1.2842x; 1.2842x over previous
#include <cuda_runtime.h>
#include <cuda_bf16.h>
#include <stdint.h>
#include <math.h>

#define BB   8
#define SS   2048
#define HH   256
#define NHH  4
#define HDD  64
#define MTOT (BB * SS)   // 16384

// ---------------------------------------------------------------------------
// Scratch (__device__ globals only).
// ---------------------------------------------------------------------------
__device__ __align__(128) __nv_bfloat16 g_Qb[32 * SS * HDD];   // [bh][s][d]
__device__ __align__(128) __nv_bfloat16 g_Kb[32 * SS * HDD];   // [bh][s][d]
__device__ __align__(128) __nv_bfloat16 g_Vt[32 * HDD * SS];   // [bh][d][s] (transposed)
__device__ __align__(128) __nv_bfloat16 g_ctxb[MTOT * HH];     // [m][h*64+d]
__device__ __align__(128) float         g_resid[MTOT * HH];

// ---------------------------------------------------------------------------
// Helpers
// ---------------------------------------------------------------------------
__device__ __forceinline__ uint32_t packbf(float lo, float hi) {
    uint32_t r;
    asm("cvt.rn.bf16x2.f32 %0, %1, %2;" : "=r"(r) : "f"(hi), "f"(lo));
    return r;
}

__device__ __forceinline__ void mma16816(float* c, const uint32_t* a, const uint32_t* b) {
    asm volatile(
        "mma.sync.aligned.m16n8k16.row.col.f32.bf16.bf16.f32 "
        "{%0,%1,%2,%3}, {%4,%5,%6,%7}, {%8,%9}, {%0,%1,%2,%3};\n"
        : "+f"(c[0]), "+f"(c[1]), "+f"(c[2]), "+f"(c[3])
        : "r"(a[0]), "r"(a[1]), "r"(a[2]), "r"(a[3]), "r"(b[0]), "r"(b[1]));
}

__device__ __forceinline__ uint32_t smem_u32(const void* p) {
    uint32_t a;
    asm("{ .reg .u64 t; cvta.to.shared.u64 t, %1; cvt.u32.u64 %0, t; }" : "=r"(a) : "l"(p));
    return a;
}

__device__ __forceinline__ void ldsm4(uint32_t& r0, uint32_t& r1, uint32_t& r2, uint32_t& r3,
                                      uint32_t addr) {
    asm volatile("ldmatrix.sync.aligned.m8n8.x4.shared.b16 {%0,%1,%2,%3}, [%4];"
                 : "=r"(r0), "=r"(r1), "=r"(r2), "=r"(r3) : "r"(addr));
}

__device__ __forceinline__ void cp16(uint32_t dst, const void* src) {
    asm volatile("cp.async.cg.shared.global [%0], [%1], 16;" :: "r"(dst), "l"(src));
}
#define CP_COMMIT() asm volatile("cp.async.commit_group;" ::: "memory")
#define CP_WAIT1()  asm volatile("cp.async.wait_group 1;" ::: "memory")
#define CP_WAIT0()  asm volatile("cp.async.wait_group 0;" ::: "memory")

#define GP 40   // smem pitch for mma.sync GEMM tiles (qkv/proj)

// ---------------------------------------------------------------------------
// Kernel 1: QKV projection (bf16 mma.sync, exact R4 version).
// Q,K split-head row-major; V transposed [bh][d][s].
// ---------------------------------------------------------------------------
__global__ __launch_bounds__(128) void qkv_kernel(
    const float* __restrict__ X,
    const float* __restrict__ Wq, const float* __restrict__ bq,
    const float* __restrict__ Wk, const float* __restrict__ bk,
    const float* __restrict__ Wv, const float* __restrict__ bv)
{
    __shared__ __nv_bfloat16 As[128 * GP];
    __shared__ __nv_bfloat16 Bs[64 * GP];

    const int z = blockIdx.z;
    const float* W;  const float* bias;
    if (z == 0)      { W = Wq; bias = bq; }
    else if (z == 1) { W = Wk; bias = bk; }
    else             { W = Wv; bias = bv; }

    const int t = threadIdx.x;
    const int w = t >> 5, lane = t & 31;
    const int g = lane >> 2, tig = lane & 3;
    const int m0 = blockIdx.y * 128, n0 = blockIdx.x * 64;

    float c[2][8][4];
    #pragma unroll
    for (int mt = 0; mt < 2; mt++)
        #pragma unroll
        for (int j = 0; j < 8; j++)
            #pragma unroll
            for (int i = 0; i < 4; i++) c[mt][j][i] = 0.0f;

    for (int k0 = 0; k0 < HH; k0 += 32) {
        #pragma unroll
        for (int i = 0; i < 8; i++) {
            int m = (t >> 3) + 16 * i;
            int k = 4 * (t & 7);
            float4 v = *(const float4*)(X + (m0 + m) * HH + k0 + k);
            uint2 p;
            p.x = packbf(v.x, v.y);
            p.y = packbf(v.z, v.w);
            *(uint2*)&As[m * GP + k] = p;
        }
        #pragma unroll
        for (int i = 0; i < 8; i++) {
            int idx = 2 * t + 256 * i;
            int k = idx >> 6, n = idx & 63;
            float2 v = *(const float2*)(W + (k0 + k) * HH + n0 + n);
            Bs[n * GP + k]       = __float2bfloat16(v.x);
            Bs[(n + 1) * GP + k] = __float2bfloat16(v.y);
        }
        __syncthreads();

        uint32_t a[2][2][4];
        #pragma unroll
        for (int mt = 0; mt < 2; mt++)
            #pragma unroll
            for (int kt = 0; kt < 2; kt++) {
                int r = w * 32 + mt * 16;
                a[mt][kt][0] = *(const uint32_t*)&As[(r + g)     * GP + kt * 16 + 2 * tig];
                a[mt][kt][1] = *(const uint32_t*)&As[(r + g + 8) * GP + kt * 16 + 2 * tig];
                a[mt][kt][2] = *(const uint32_t*)&As[(r + g)     * GP + kt * 16 + 2 * tig + 8];
                a[mt][kt][3] = *(const uint32_t*)&As[(r + g + 8) * GP + kt * 16 + 2 * tig + 8];
            }
        #pragma unroll
        for (int j = 0; j < 8; j++) {
            #pragma unroll
            for (int kt = 0; kt < 2; kt++) {
                uint32_t b[2];
                b[0] = *(const uint32_t*)&Bs[(8 * j + g) * GP + kt * 16 + 2 * tig];
                b[1] = *(const uint32_t*)&Bs[(8 * j + g) * GP + kt * 16 + 2 * tig + 8];
                mma16816(c[0][j], a[0][kt], b);
                mma16816(c[1][j], a[1][kt], b);
            }
        }
        __syncthreads();
    }

    const int head = blockIdx.x;
    #pragma unroll
    for (int mt = 0; mt < 2; mt++) {
        int r0 = m0 + w * 32 + mt * 16 + g;
        #pragma unroll
        for (int half = 0; half < 2; half++) {
            int m  = r0 + half * 8;
            int b_ = m >> 11;
            int s_ = m & (SS - 1);
            int bh = b_ * NHH + head;
            #pragma unroll
            for (int j = 0; j < 8; j++) {
                int d = 8 * j + 2 * tig;
                float v0 = c[mt][j][half * 2 + 0] + bias[n0 + d];
                float v1 = c[mt][j][half * 2 + 1] + bias[n0 + d + 1];
                if (z == 0) {
                    *(uint32_t*)&g_Qb[(bh * SS + s_) * HDD + d] = packbf(v0, v1);
                } else if (z == 1) {
                    *(uint32_t*)&g_Kb[(bh * SS + s_) * HDD + d] = packbf(v0, v1);
                } else {
                    g_Vt[(bh * HDD + d)     * SS + s_] = __float2bfloat16(v0);
                    g_Vt[(bh * HDD + d + 1) * SS + s_] = __float2bfloat16(v1);
                }
            }
        }
    }
}

// ---------------------------------------------------------------------------
// Kernel 2: flash attention (R4 base) + mask staged through smem via cp.async.
// BQ=128 (32 rows/warp), BK=64, 2-buffer K/V/mask pipeline, wait_group 1.
// Dynamic smem layout (102400 B):
//   K0 @0, K1 @8192, V0 @16384, V1 @24576 (each 64x128B, swizzled)
//   M0 @32768, M1 @67584 (each 128 rows x 68 floats = 34816 B)
// ---------------------------------------------------------------------------
#define NIT 32            // SS / 64
#define SM_K0   0
#define SM_K1   8192
#define SM_V0   16384
#define SM_V1   24576
#define SM_M0   32768
#define SM_M1   67584
#define MPITCH  68        // floats per mask row (272 B, 16B-aligned)
#define ATTN_SMEM 102400

__global__ __launch_bounds__(128) void attn_kernel(const float* __restrict__ mask)
{
    extern __shared__ char dynsm[];

    const int t = threadIdx.x;
    const int w = t >> 5, lane = t & 31;
    const int g = lane >> 2, tig = lane & 3;
    const int bh = blockIdx.x;
    const int qb = blockIdx.y;
    const int b_ = bh >> 2;
    const int h_ = bh & 3;

    const uint32_t smb = smem_u32(dynsm);
    const uint32_t kbase[2] = { smb + SM_K0, smb + SM_K1 };
    const uint32_t vbase[2] = { smb + SM_V0, smb + SM_V1 };
    const uint32_t mbase[2] = { smb + SM_M0, smb + SM_M1 };
    float* const msm[2] = { (float*)(dynsm + SM_M0), (float*)(dynsm + SM_M1) };

    const __nv_bfloat16* Qg = g_Qb + (size_t)bh * SS * HDD;
    const char* Kg = (const char*)(g_Kb + (size_t)bh * SS * HDD);
    const char* Vg = (const char*)(g_Vt + (size_t)bh * HDD * SS);
    const float* Mb = mask + (size_t)b_ * SS * SS + (size_t)(qb * 128) * SS;

    // K/V cp.async chunk addressing: chunk c = t + 128*jc -> row (0..63), seg (0..7)
    int ld_src[4], ld_dst[4], ld_row[4];
    #pragma unroll
    for (int jc = 0; jc < 4; jc++) {
        int c = t + 128 * jc;
        int row = c >> 3, seg = c & 7;
        ld_row[jc] = row;
        ld_src[jc] = row * 128 + seg * 16;
        ld_dst[jc] = row * 128 + ((seg * 16) ^ ((row & 7) * 16));
    }
    // Mask chunk addressing: chunk c = t + 128*jm -> row (0..127), seg (0..15)
    int md_dst[16];
    int md_row[16];
    #pragma unroll
    for (int jm = 0; jm < 16; jm++) {
        int c = t + 128 * jm;
        int row = c >> 4, seg = c & 15;
        md_row[jm] = row;
        md_dst[jm] = row * (MPITCH * 4) + seg * 16;
    }

    // ldmatrix addressing (B-frags for both S and PV loops)
    const int lrow = (lane & 7) | ((lane & 16) >> 1);
    const int lkb  = (lane & 8) ? 16 : 0;
    const int lxor = (lrow & 7) * 16;
    const int lbase = lrow * 128;

    // Q A-fragments (2 m-tiles of 16 rows), resident all iterations
    const int qrow[2] = { qb * 128 + w * 32 + g, qb * 128 + w * 32 + 16 + g };
    uint32_t aq[2][4][4];
    #pragma unroll
    for (int mt = 0; mt < 2; mt++) {
        const __nv_bfloat16* r0 = Qg + (size_t)qrow[mt] * HDD;
        const __nv_bfloat16* r1 = r0 + 8 * HDD;
        #pragma unroll
        for (int kt = 0; kt < 4; kt++) {
            aq[mt][kt][0] = *(const uint32_t*)(r0 + kt * 16 + 2 * tig);
            aq[mt][kt][1] = *(const uint32_t*)(r1 + kt * 16 + 2 * tig);
            aq[mt][kt][2] = *(const uint32_t*)(r0 + kt * 16 + 2 * tig + 8);
            aq[mt][kt][3] = *(const uint32_t*)(r1 + kt * 16 + 2 * tig + 8);
        }
    }

    // tile loader: K tile [kv][d], V tile [d][kv], mask tile 128x64
    auto load_tiles = [&](int it, int buf) {
        const char* Ks = Kg + (size_t)it * 64 * 128;
        #pragma unroll
        for (int jc = 0; jc < 4; jc++) {
            cp16(kbase[buf] + ld_dst[jc], Ks + ld_src[jc]);
            cp16(vbase[buf] + ld_dst[jc],
                 Vg + (size_t)ld_row[jc] * (SS * 2) + it * 128 + (t & 7) * 16);
        }
        #pragma unroll
        for (int jm = 0; jm < 16; jm++) {
            cp16(mbase[buf] + md_dst[jm],
                 (const char*)(Mb + (size_t)md_row[jm] * SS + it * 64) + (t & 15) * 16);
        }
        CP_COMMIT();
    };

    // prologue: tiles 0 and 1
    load_tiles(0, 0);
    load_tiles(1, 1);

    float o[2][8][4];
    #pragma unroll
    for (int mt = 0; mt < 2; mt++)
        #pragma unroll
        for (int j = 0; j < 8; j++)
            #pragma unroll
            for (int i = 0; i < 4; i++) o[mt][j][i] = 0.0f;
    float lacc[2][2] = {{0.0f, 0.0f}, {0.0f, 0.0f}};

    for (int i = 0; i < NIT; i++) {
        const int buf = i & 1;
        if (i < NIT - 1) { CP_WAIT1(); } else { CP_WAIT0(); }
        __syncthreads();

        // ---- S = Q @ K^T ----
        float c[2][8][4];
        #pragma unroll
        for (int mt = 0; mt < 2; mt++)
            #pragma unroll
            for (int j = 0; j < 8; j++)
                #pragma unroll
                for (int q = 0; q < 4; q++) c[mt][j][q] = 0.0f;

        #pragma unroll
        for (int jj = 0; jj < 4; jj++) {
            #pragma unroll
            for (int kt = 0; kt < 4; kt++) {
                uint32_t r0, r1, r2, r3;
                ldsm4(r0, r1, r2, r3,
                      kbase[buf] + jj * 2048 + lbase + ((kt * 32 + lkb) ^ lxor));
                uint32_t blo[2] = { r0, r1 }, bhi[2] = { r2, r3 };
                mma16816(c[0][2 * jj],     aq[0][kt], blo);
                mma16816(c[0][2 * jj + 1], aq[0][kt], bhi);
                mma16816(c[1][2 * jj],     aq[1][kt], blo);
                mma16816(c[1][2 * jj + 1], aq[1][kt], bhi);
            }
        }

        // ---- softmax (no max): p = exp(s/8 + mask), mask from SMEM ----
        uint32_t pa[2][4][4];
        #pragma unroll
        for (int mt = 0; mt < 2; mt++) {
            const float* mp0 = msm[buf] + (w * 32 + mt * 16 + g) * MPITCH + 2 * tig;
            const float* mp1 = mp0 + 8 * MPITCH;
            #pragma unroll
            for (int j = 0; j < 8; j++) {
                float2 mk0 = *(const float2*)(mp0 + 8 * j);
                float2 mk1 = *(const float2*)(mp1 + 8 * j);
                float p0 = __expf(fmaf(c[mt][j][0], 0.125f, mk0.x));
                float p1 = __expf(fmaf(c[mt][j][1], 0.125f, mk0.y));
                float p2 = __expf(fmaf(c[mt][j][2], 0.125f, mk1.x));
                float p3 = __expf(fmaf(c[mt][j][3], 0.125f, mk1.y));
                lacc[mt][0] += p0 + p1;
                lacc[mt][1] += p2 + p3;
                int kt = j >> 1, hi = (j & 1) * 2;
                pa[mt][kt][hi + 0] = packbf(p0, p1);
                pa[mt][kt][hi + 1] = packbf(p2, p3);
            }
        }

        // ---- O += P @ V (V tile is [d][kv], non-trans ldmatrix) ----
        #pragma unroll
        for (int jj = 0; jj < 4; jj++) {
            #pragma unroll
            for (int kt = 0; kt < 4; kt++) {
                uint32_t r0, r1, r2, r3;
                ldsm4(r0, r1, r2, r3,
                      vbase[buf] + jj * 2048 + lbase + ((kt * 32 + lkb) ^ lxor));
                uint32_t blo[2] = { r0, r1 }, bhi[2] = { r2, r3 };
                mma16816(o[0][2 * jj],     pa[0][kt], blo);
                mma16816(o[0][2 * jj + 1], pa[0][kt], bhi);
                mma16816(o[1][2 * jj],     pa[1][kt], blo);
                mma16816(o[1][2 * jj + 1], pa[1][kt], bhi);
            }
        }

        __syncthreads();   // everyone done reading buf before it is overwritten

        if (i + 2 < NIT) load_tiles(i + 2, buf);
    }

    // ---- final: reduce l across the 4 lanes of each row group, write ctx ----
    #pragma unroll
    for (int mt = 0; mt < 2; mt++)
        #pragma unroll
        for (int h = 0; h < 2; h++) {
            float v = lacc[mt][h];
            v += __shfl_xor_sync(0xffffffffu, v, 1);
            v += __shfl_xor_sync(0xffffffffu, v, 2);
            lacc[mt][h] = 1.0f / v;
        }

    #pragma unroll
    for (int mt = 0; mt < 2; mt++) {
        __nv_bfloat16* c0 = g_ctxb + ((size_t)b_ * SS + qrow[mt]) * HH + h_ * HDD;
        __nv_bfloat16* c1 = c0 + 8 * HH;
        #pragma unroll
        for (int j = 0; j < 8; j++) {
            int d = 8 * j + 2 * tig;
            *(uint32_t*)(c0 + d) = packbf(o[mt][j][0] * lacc[mt][0],
                                          o[mt][j][1] * lacc[mt][0]);
            *(uint32_t*)(c1 + d) = packbf(o[mt][j][2] * lacc[mt][1],
                                          o[mt][j][3] * lacc[mt][1]);
        }
    }
}

// ---------------------------------------------------------------------------
// Kernel 3: out projection + residual (bf16 mma.sync, unchanged)
// ---------------------------------------------------------------------------
__global__ __launch_bounds__(128) void proj_kernel(
    const float* __restrict__ X,
    const float* __restrict__ Wo, const float* __restrict__ bo)
{
    __shared__ __nv_bfloat16 As[128 * GP];
    __shared__ __nv_bfloat16 Bs[64 * GP];

    const int t = threadIdx.x;
    const int w = t >> 5, lane = t & 31;
    const int g = lane >> 2, tig = lane & 3;
    const int m0 = blockIdx.y * 128, n0 = blockIdx.x * 64;

    float c[2][8][4];
    #pragma unroll
    for (int mt = 0; mt < 2; mt++)
        #pragma unroll
        for (int j = 0; j < 8; j++)
            #pragma unroll
            for (int i = 0; i < 4; i++) c[mt][j][i] = 0.0f;

    for (int k0 = 0; k0 < HH; k0 += 32) {
        #pragma unroll
        for (int i = 0; i < 4; i++) {
            int m = (t >> 2) + 32 * i;
            int k = 8 * (t & 3);
            *(uint4*)&As[m * GP + k] =
                *(const uint4*)&g_ctxb[(m0 + m) * HH + k0 + k];
        }
        #pragma unroll
        for (int i = 0; i < 8; i++) {
            int idx = 2 * t + 256 * i;
            int k = idx >> 6, n = idx & 63;
            float2 v = *(const float2*)(Wo + (k0 + k) * HH + n0 + n);
            Bs[n * GP + k]       = __float2bfloat16(v.x);
            Bs[(n + 1) * GP + k] = __float2bfloat16(v.y);
        }
        __syncthreads();

        uint32_t a[2][2][4];
        #pragma unroll
        for (int mt = 0; mt < 2; mt++)
            #pragma unroll
            for (int kt = 0; kt < 2; kt++) {
                int r = w * 32 + mt * 16;
                a[mt][kt][0] = *(const uint32_t*)&As[(r + g)     * GP + kt * 16 + 2 * tig];
                a[mt][kt][1] = *(const uint32_t*)&As[(r + g + 8) * GP + kt * 16 + 2 * tig];
                a[mt][kt][2] = *(const uint32_t*)&As[(r + g)     * GP + kt * 16 + 2 * tig + 8];
                a[mt][kt][3] = *(const uint32_t*)&As[(r + g + 8) * GP + kt * 16 + 2 * tig + 8];
            }
        #pragma unroll
        for (int j = 0; j < 8; j++) {
            #pragma unroll
            for (int kt = 0; kt < 2; kt++) {
                uint32_t b[2];
                b[0] = *(const uint32_t*)&Bs[(8 * j + g) * GP + kt * 16 + 2 * tig];
                b[1] = *(const uint32_t*)&Bs[(8 * j + g) * GP + kt * 16 + 2 * tig + 8];
                mma16816(c[0][j], a[0][kt], b);
                mma16816(c[1][j], a[1][kt], b);
            }
        }
        __syncthreads();
    }

    #pragma unroll
    for (int mt = 0; mt < 2; mt++) {
        int r0 = m0 + w * 32 + mt * 16 + g;
        #pragma unroll
        for (int half = 0; half < 2; half++) {
            int m = r0 + half * 8;
            #pragma unroll
            for (int j = 0; j < 8; j++) {
                int n = n0 + 8 * j + 2 * tig;
                float2 xr = *(const float2*)(X + m * HH + n);
                float2 ov;
                ov.x = c[mt][j][half * 2 + 0] + bo[n]     + xr.x;
                ov.y = c[mt][j][half * 2 + 1] + bo[n + 1] + xr.y;
                *(float2*)&g_resid[m * HH + n] = ov;
            }
        }
    }
}

// ---------------------------------------------------------------------------
// Kernel 4: LayerNorm (unchanged)
// ---------------------------------------------------------------------------
__global__ __launch_bounds__(256) void ln_kernel(
    const float* __restrict__ gamma, const float* __restrict__ beta,
    float* __restrict__ out)
{
    const int lane = threadIdx.x & 31;
    const int warp = threadIdx.x >> 5;
    const int row  = blockIdx.x * 8 + warp;

    const float* r = g_resid + row * HH + lane * 8;
    float4 a  = *(const float4*)(r);
    float4 b4 = *(const float4*)(r + 4);

    float sum = a.x + a.y + a.z + a.w + b4.x + b4.y + b4.z + b4.w;
    #pragma unroll
    for (int off = 16; off; off >>= 1)
        sum += __shfl_xor_sync(0xffffffffu, sum, off);
    float mu = sum * (1.0f / 256.0f);

    float d0 = a.x - mu, d1 = a.y - mu, d2 = a.z - mu, d3 = a.w - mu;
    float d4 = b4.x - mu, d5 = b4.y - mu, d6 = b4.z - mu, d7 = b4.w - mu;
    float vs = d0 * d0 + d1 * d1 + d2 * d2 + d3 * d3
             + d4 * d4 + d5 * d5 + d6 * d6 + d7 * d7;
    #pragma unroll
    for (int off = 16; off; off >>= 1)
        vs += __shfl_xor_sync(0xffffffffu, vs, off);
    float inv = rsqrtf(vs * (1.0f / 256.0f) + 1e-12f);

    float4 g0 = *(const float4*)(gamma + lane * 8);
    float4 g1 = *(const float4*)(gamma + lane * 8 + 4);
    float4 e0 = *(const float4*)(beta + lane * 8);
    float4 e1 = *(const float4*)(beta + lane * 8 + 4);

    float4 o0, o1;
    o0.x = d0 * inv * g0.x + e0.x;
    o0.y = d1 * inv * g0.y + e0.y;
    o0.z = d2 * inv * g0.z + e0.z;
    o0.w = d3 * inv * g0.w + e0.w;
    o1.x = d4 * inv * g1.x + e1.x;
    o1.y = d5 * inv * g1.y + e1.y;
    o1.z = d6 * inv * g1.z + e1.z;
    o1.w = d7 * inv * g1.w + e1.w;

    float* op = out + row * HH + lane * 8;
    *(float4*)(op)     = o0;
    *(float4*)(op + 4) = o1;
}

// ---------------------------------------------------------------------------
extern "C" void kernel_launch(void* const* d_in, const int* in_sizes, int n_in,
                              void* d_out, int out_size)
{
    const float* X     = (const float*)d_in[0];
    const float* mask  = (const float*)d_in[1];
    const float* Wq    = (const float*)d_in[2];
    const float* bq    = (const float*)d_in[3];
    const float* Wk    = (const float*)d_in[4];
    const float* bk    = (const float*)d_in[5];
    const float* Wv    = (const float*)d_in[6];
    const float* bv    = (const float*)d_in[7];
    const float* Wo    = (const float*)d_in[8];
    const float* bo    = (const float*)d_in[9];
    const float* gamma = (const float*)d_in[10];
    const float* beta  = (const float*)d_in[11];
    float* out = (float*)d_out;

    cudaFuncSetAttribute(attn_kernel,
                         cudaFuncAttributeMaxDynamicSharedMemorySize, ATTN_SMEM);

    qkv_kernel<<<dim3(HH / 64, MTOT / 128, 3), 128>>>(X, Wq, bq, Wk, bk, Wv, bv);
    attn_kernel<<<dim3(BB * NHH, SS / 128), 128, ATTN_SMEM>>>(mask);
    proj_kernel<<<dim3(HH / 64, MTOT / 128), 128>>>(X, Wo, bo);
    ln_kernel<<<MTOT / 8, 256>>>(gamma, beta, out);
}